// round 11
// baseline (speedup 1.0000x reference)
#include <cuda_runtime.h>
#include <cstdint>

#define NDIM 8192
#define THREADS 256
#define NBLOCKS 592                 // 148 SMs * 4 CTAs/SM -> one wave
#define NWARPS (NBLOCKS * 8)        // 4736
#define NITEMS (NDIM * 8)           // 65536 row-eighth items (4 KB each)
#define CTR_SEED (2 * NWARPS)       // dynamic grabs start after 2 static seeds

// Scratch (no cudaMalloc allowed).
__device__ float g_partA[NBLOCKS];
__device__ float g_partB[NBLOCKS];
__device__ int   g_ctr   = CTR_SEED;   // work-stealing counter
__device__ int   g_count = 0;          // completion counter

// Packed f32x2 helpers (sm_103a).
__device__ __forceinline__ void fma2(unsigned long long& d,
                                     unsigned long long a,
                                     unsigned long long b) {
    asm("fma.rn.f32x2 %0, %1, %2, %0;" : "+l"(d) : "l"(a), "l"(b));
}
__device__ __forceinline__ void add2(unsigned long long& d,
                                     unsigned long long a) {
    asm("add.rn.f32x2 %0, %0, %1;" : "+l"(d) : "l"(a));
}
__device__ __forceinline__ float lo2(unsigned long long p) {
    unsigned int l, h;
    asm("mov.b64 {%0, %1}, %2;" : "=r"(l), "=r"(h) : "l"(p));
    return __uint_as_float(l);
}
__device__ __forceinline__ float hi2(unsigned long long p) {
    unsigned int l, h;
    asm("mov.b64 {%0, %1}, %2;" : "=r"(l), "=r"(h) : "l"(p));
    return __uint_as_float(h);
}

__global__ __launch_bounds__(THREADS, 4)
void ising_fused(const float* __restrict__ M, const float* __restrict__ s,
                 float* __restrict__ out) {
    __shared__ float s_sh[NDIM];          // 32 KB staged state vector
    __shared__ float sA[THREADS / 32];
    __shared__ float sB[THREADS / 32];
    __shared__ int s_isLast;

    const int tid  = threadIdx.x;
    const int lane = tid & 31;
    const int wid  = tid >> 5;
    const int gwid = blockIdx.x * 8 + wid;   // global warp id

    // Stage state vector into shared (vectorized, coalesced).
    {
        const float4* s4g = reinterpret_cast<const float4*>(s);
        float4* sh4w = reinterpret_cast<float4*>(s_sh);
        #pragma unroll
        for (int k = tid; k < NDIM / 4; k += THREADS) sh4w[k] = s4g[k];
    }
    __syncthreads();

    const ulonglong2* s64 = reinterpret_cast<const ulonglong2*>(s_sh);
    const ulonglong2* M64 = reinterpret_cast<const ulonglong2*>(M);

    unsigned long long a01 = 0ull, a23 = 0ull;   // packed plain sum (all items)
    float amAcc = 0.0f;                          // mixed-vec plain remainder
    float bAcc  = 0.0f;                          // s_i-weighted upper-dot + diag

    // Two grabs ahead: t0 in flight, t1 known, t2 fetched this iteration.
    int t0 = gwid;
    int t1 = gwid + NWARPS;

    // Prologue: issue loads for t0 (8 independent coalesced LDG.128, MLP=8).
    ulonglong2 v[8];
    {
        const size_t base = (size_t)(t0 >> 3) * 2048 + (t0 & 7) * 256 + lane;
        #pragma unroll
        for (int m = 0; m < 8; ++m) v[m] = __ldg(M64 + base + m * 32);
    }

    #pragma unroll 1
    while (t0 < NITEMS) {
        // Issue next-next grab (result consumed only after the consume phase).
        int grabbed = 0;
        if (lane == 0) grabbed = atomicAdd(&g_ctr, 1);

        // ---- Consume item t0 ----
        const int row  = t0 >> 3;
        const int vbase = (t0 & 7) * 256;
        const int vs   = row >> 2;            // vec index containing the diagonal
        const float srow = s_sh[row];

        unsigned long long d01 = 0ull, d23 = 0ull;
        float dm = 0.0f;

        #pragma unroll
        for (int m = 0; m < 8; ++m) {
            const int j4 = vbase + m * 32 + lane;
            const ulonglong2 vv = v[m];
            if (j4 > vs) {
                const ulonglong2 tt = s64[j4];      // LDS.128, conflict-free
                add2(a01, vv.x);  add2(a23, vv.y);
                fma2(d01, vv.x, tt.x);  fma2(d23, vv.y, tt.y);
            } else if (j4 < vs) {
                add2(a01, vv.x);  add2(a23, vv.y);
            } else {
                const float vx = lo2(vv.x), vy = hi2(vv.x);
                const float vz = lo2(vv.y), vw = hi2(vv.y);
                const ulonglong2 tt = s64[j4];
                const float tx = lo2(tt.x), ty = hi2(tt.x);
                const float tz = lo2(tt.y), tw = hi2(tt.y);
                const int j = j4 * 4;
                amAcc += (vx + vy) + (vz + vw);
                const float w0 = (j + 0 > row) ? tx : ((j + 0 == row) ? 1.0f : 0.0f);
                const float w1 = (j + 1 > row) ? ty : ((j + 1 == row) ? 1.0f : 0.0f);
                const float w2 = (j + 2 > row) ? tz : ((j + 2 == row) ? 1.0f : 0.0f);
                const float w3 = (j + 3 > row) ? tw : ((j + 3 == row) ? 1.0f : 0.0f);
                dm += fmaf(vx, w0, fmaf(vy, w1, fmaf(vz, w2, vw * w3)));
            }
        }

        const float di = ((lo2(d01) + hi2(d01)) + (lo2(d23) + hi2(d23))) + dm;
        bAcc = fmaf(srow, di, bAcc);

        // ---- Issue loads for t1 (if valid) ----
        if (t1 < NITEMS) {
            const size_t base = (size_t)(t1 >> 3) * 2048 + (t1 & 7) * 256 + lane;
            #pragma unroll
            for (int m = 0; m < 8; ++m) v[m] = __ldg(M64 + base + m * 32);
        }

        // Rotate the grab pipeline (atomic has had the whole consume to land).
        const int t2 = __shfl_sync(0xFFFFFFFFu, grabbed, 0);
        t0 = t1;
        t1 = t2;
    }

    float aAcc = ((lo2(a01) + hi2(a01)) + (lo2(a23) + hi2(a23))) + amAcc;

    // Warp shuffle reduction (fixed order within warp).
    #pragma unroll
    for (int off = 16; off > 0; off >>= 1) {
        aAcc += __shfl_xor_sync(0xFFFFFFFFu, aAcc, off);
        bAcc += __shfl_xor_sync(0xFFFFFFFFu, bAcc, off);
    }
    if (lane == 0) { sA[wid] = aAcc; sB[wid] = bAcc; }
    __syncthreads();

    if (tid == 0) {
        float a = 0.f, b = 0.f;
        #pragma unroll
        for (int w = 0; w < THREADS / 32; ++w) { a += sA[w]; b += sB[w]; }
        g_partA[blockIdx.x] = a;
        g_partB[blockIdx.x] = b;
        __threadfence();
        const int prev = atomicAdd(&g_count, 1);
        s_isLast = (prev == NBLOCKS - 1);
    }
    __syncthreads();

    // Last block: deterministic final reduction in double (reuses s_sh space).
    if (s_isLast) {
        double* rA = reinterpret_cast<double*>(s_sh);
        double* rB = rA + THREADS;
        double a = 0.0, b = 0.0;
        #pragma unroll 2
        for (int k = tid; k < NBLOCKS; k += THREADS) {
            a += (double)g_partA[k];
            b += (double)g_partB[k];
        }
        rA[tid] = a;
        rB[tid] = b;
        __syncthreads();
        #pragma unroll
        for (int st = THREADS / 2; st > 0; st >>= 1) {
            if (tid < st) { rA[tid] += rA[tid + st]; rB[tid] += rB[tid + st]; }
            __syncthreads();
        }
        if (tid == 0) {
            // out = sum(M)/4 - 0.5 * (sum_{i<j} M_ij s_i s_j + sum_i M_ii s_i)
            out[0] = (float)(rA[0] * 0.25 - 0.5 * rB[0]);
            g_count = 0;          // reset for next graph replay
            g_ctr = CTR_SEED;
        }
    }
}

extern "C" void kernel_launch(void* const* d_in, const int* in_sizes, int n_in,
                              void* d_out, int out_size) {
    const float* M = (const float*)d_in[0];   // info_mtx [8192, 8192] fp32
    const float* s = (const float*)d_in[1];   // state [8192] fp32
    float* out = (float*)d_out;

    ising_fused<<<NBLOCKS, THREADS>>>(M, s, out);
}

// round 12
// speedup vs baseline: 1.2161x; 1.2161x over previous
#include <cuda_runtime.h>
#include <cstdint>

#define NDIM 8192
#define THREADS 256
#define NBLOCKS 444                    // 148 SMs * 3 CTAs/SM -> one wave at <=85 regs

// Scratch for deterministic two-stage reduction (no cudaMalloc allowed).
__device__ float g_partA[NBLOCKS];
__device__ float g_partB[NBLOCKS];
__device__ int   g_count = 0;

// Packed f32x2 helpers (sm_103a).
__device__ __forceinline__ void fma2(unsigned long long& d,
                                     unsigned long long a,
                                     unsigned long long b) {
    asm("fma.rn.f32x2 %0, %1, %2, %0;" : "+l"(d) : "l"(a), "l"(b));
}
__device__ __forceinline__ void add2(unsigned long long& d,
                                     unsigned long long a) {
    asm("add.rn.f32x2 %0, %0, %1;" : "+l"(d) : "l"(a));
}
__device__ __forceinline__ float lo2(unsigned long long p) {
    unsigned int l, h;
    asm("mov.b64 {%0, %1}, %2;" : "=r"(l), "=r"(h) : "l"(p));
    return __uint_as_float(l);
}
__device__ __forceinline__ float hi2(unsigned long long p) {
    unsigned int l, h;
    asm("mov.b64 {%0, %1}, %2;" : "=r"(l), "=r"(h) : "l"(p));
    return __uint_as_float(h);
}

__global__ __launch_bounds__(THREADS, 3)
void ising_fused(const float* __restrict__ M, const float* __restrict__ s,
                 float* __restrict__ out) {
    __shared__ float s_sh[NDIM];          // 32 KB staged state vector
    __shared__ float sA[THREADS / 32];
    __shared__ float sB[THREADS / 32];
    __shared__ int s_isLast;

    const int tid  = threadIdx.x;
    const int lane = tid & 31;
    const int wid  = tid >> 5;
    const int bid  = blockIdx.x;

    // Stage state vector into shared (vectorized, coalesced).
    {
        const float4* s4g = reinterpret_cast<const float4*>(s);
        float4* sh4w = reinterpret_cast<float4*>(s_sh);
        #pragma unroll
        for (int k = tid; k < NDIM / 4; k += THREADS) sh4w[k] = s4g[k];
    }
    __syncthreads();

    const ulonglong2* s64 = reinterpret_cast<const ulonglong2*>(s_sh);

    // Contiguous row partition: 8192 rows over 444 CTAs (18 or 19 each).
    const int rowBeg = (int)(((long long)bid * NDIM) / NBLOCKS);
    const int rowEnd = (int)(((long long)(bid + 1) * NDIM) / NBLOCKS);
    const int n = rowEnd - rowBeg;

    unsigned long long a01 = 0ull, a23 = 0ull;   // packed plain sum
    float amAcc = 0.0f;                          // mixed-vec plain remainder
    float bAcc  = 0.0f;                          // s_i-weighted upper-dot + diag

    ulonglong2 vA[8], vB[8];   // double-buffered row registers (64 regs)

    auto loadRow = [&](ulonglong2* buf, int row) {
        const ulonglong2* r64 =
            reinterpret_cast<const ulonglong2*>(M + (size_t)row * NDIM);
        #pragma unroll
        for (int m = 0; m < 8; ++m) buf[m] = __ldg(r64 + tid + m * 256);
    };

    auto consumeRow = [&](const ulonglong2* buf, int row) {
        const int vs = row >> 2;          // vec index containing the diagonal
        unsigned long long d01 = 0ull, d23 = 0ull;
        float dm = 0.0f;
        #pragma unroll
        for (int m = 0; m < 8; ++m) {
            const int j4 = tid + m * 256;
            const ulonglong2 vv = buf[m];
            if (j4 > vs) {
                const ulonglong2 tt = s64[j4];       // LDS.128, conflict-free
                add2(a01, vv.x);  add2(a23, vv.y);
                fma2(d01, vv.x, tt.x);  fma2(d23, vv.y, tt.y);
            } else if (j4 < vs) {
                add2(a01, vv.x);  add2(a23, vv.y);
            } else {
                const float vx = lo2(vv.x), vy = hi2(vv.x);
                const float vz = lo2(vv.y), vw = hi2(vv.y);
                const ulonglong2 tt = s64[j4];
                const float tx = lo2(tt.x), ty = hi2(tt.x);
                const float tz = lo2(tt.y), tw = hi2(tt.y);
                const int j = j4 * 4;
                amAcc += (vx + vy) + (vz + vw);
                const float w0 = (j + 0 > row) ? tx : ((j + 0 == row) ? 1.0f : 0.0f);
                const float w1 = (j + 1 > row) ? ty : ((j + 1 == row) ? 1.0f : 0.0f);
                const float w2 = (j + 2 > row) ? tz : ((j + 2 == row) ? 1.0f : 0.0f);
                const float w3 = (j + 3 > row) ? tw : ((j + 3 == row) ? 1.0f : 0.0f);
                dm += fmaf(vx, w0, fmaf(vy, w1, fmaf(vz, w2, vw * w3)));
            }
        }
        const float di = ((lo2(d01) + hi2(d01)) + (lo2(d23) + hi2(d23))) + dm;
        bAcc = fmaf(s_sh[row], di, bAcc);
    };

    // Software pipeline: while consuming row k, row k+1's loads are in flight.
    loadRow(vA, rowBeg);
    int k = 0;
    #pragma unroll 1
    for (; k + 2 <= n; k += 2) {
        loadRow(vB, rowBeg + k + 1);          // issue before consuming vA
        consumeRow(vA, rowBeg + k);
        if (k + 2 < n) loadRow(vA, rowBeg + k + 2);
        consumeRow(vB, rowBeg + k + 1);
    }
    if (k < n) consumeRow(vA, rowBeg + k);    // odd-count tail

    float aAcc = ((lo2(a01) + hi2(a01)) + (lo2(a23) + hi2(a23))) + amAcc;

    // Warp shuffle reduction (deterministic).
    #pragma unroll
    for (int off = 16; off > 0; off >>= 1) {
        aAcc += __shfl_xor_sync(0xFFFFFFFFu, aAcc, off);
        bAcc += __shfl_xor_sync(0xFFFFFFFFu, bAcc, off);
    }
    if (lane == 0) { sA[wid] = aAcc; sB[wid] = bAcc; }
    __syncthreads();

    if (tid == 0) {
        float a = 0.f, b = 0.f;
        #pragma unroll
        for (int w = 0; w < THREADS / 32; ++w) { a += sA[w]; b += sB[w]; }
        g_partA[bid] = a;
        g_partB[bid] = b;
        __threadfence();
        const int prev = atomicAdd(&g_count, 1);
        s_isLast = (prev == NBLOCKS - 1);
    }
    __syncthreads();

    // Last block: deterministic final reduction in double (reuses s_sh space).
    if (s_isLast) {
        double* rA = reinterpret_cast<double*>(s_sh);
        double* rB = rA + THREADS;
        double a = 0.0, b = 0.0;
        #pragma unroll 2
        for (int kk = tid; kk < NBLOCKS; kk += THREADS) {
            a += (double)g_partA[kk];
            b += (double)g_partB[kk];
        }
        rA[tid] = a;
        rB[tid] = b;
        __syncthreads();
        #pragma unroll
        for (int st = THREADS / 2; st > 0; st >>= 1) {
            if (tid < st) { rA[tid] += rA[tid + st]; rB[tid] += rB[tid + st]; }
            __syncthreads();
        }
        if (tid == 0) {
            // out = sum(M)/4 - 0.5 * (sum_{i<j} M_ij s_i s_j + sum_i M_ii s_i)
            out[0] = (float)(rA[0] * 0.25 - 0.5 * rB[0]);
            g_count = 0;   // reset for next graph replay
        }
    }
}

extern "C" void kernel_launch(void* const* d_in, const int* in_sizes, int n_in,
                              void* d_out, int out_size) {
    const float* M = (const float*)d_in[0];   // info_mtx [8192, 8192] fp32
    const float* s = (const float*)d_in[1];   // state [8192] fp32
    float* out = (float*)d_out;

    ising_fused<<<NBLOCKS, THREADS>>>(M, s, out);
}

// round 13
// speedup vs baseline: 1.5202x; 1.2500x over previous
#include <cuda_runtime.h>
#include <cstdint>

#define NDIM 8192
#define THREADS 256
#define NBLOCKS 592                    // 148 SMs * 4 CTAs/SM -> one wave at <=64 regs

// Scratch for deterministic two-stage reduction (no cudaMalloc allowed).
__device__ float g_partA[NBLOCKS];
__device__ float g_partB[NBLOCKS];
__device__ int   g_count = 0;

// Packed f32x2 helpers (sm_103a).
__device__ __forceinline__ void fma2(unsigned long long& d,
                                     unsigned long long a,
                                     unsigned long long b) {
    asm("fma.rn.f32x2 %0, %1, %2, %0;" : "+l"(d) : "l"(a), "l"(b));
}
__device__ __forceinline__ void add2(unsigned long long& d,
                                     unsigned long long a) {
    asm("add.rn.f32x2 %0, %0, %1;" : "+l"(d) : "l"(a));
}
__device__ __forceinline__ float lo2(unsigned long long p) {
    unsigned int l, h;
    asm("mov.b64 {%0, %1}, %2;" : "=r"(l), "=r"(h) : "l"(p));
    return __uint_as_float(l);
}
__device__ __forceinline__ float hi2(unsigned long long p) {
    unsigned int l, h;
    asm("mov.b64 {%0, %1}, %2;" : "=r"(l), "=r"(h) : "l"(p));
    return __uint_as_float(h);
}

__global__ __launch_bounds__(THREADS, 4)
void ising_fused(const float* __restrict__ M, const float* __restrict__ s,
                 float* __restrict__ out) {
    __shared__ float s_sh[NDIM];          // 32 KB staged state vector
    __shared__ float sA[THREADS / 32];
    __shared__ float sB[THREADS / 32];
    __shared__ int s_isLast;

    const int tid  = threadIdx.x;
    const int lane = tid & 31;
    const int wid  = tid >> 5;
    const int bid  = blockIdx.x;

    // Stage state vector into shared (vectorized, coalesced).
    {
        const float4* s4g = reinterpret_cast<const float4*>(s);
        float4* sh4w = reinterpret_cast<float4*>(s_sh);
        #pragma unroll
        for (int k = tid; k < NDIM / 4; k += THREADS) sh4w[k] = s4g[k];
    }
    __syncthreads();

    const ulonglong2* s64 = reinterpret_cast<const ulonglong2*>(s_sh);

    // Contiguous row partition: 8192 rows over 592 CTAs (13 or 14 each).
    const int rowBeg = (int)(((long long)bid * NDIM) / NBLOCKS);
    const int rowEnd = (int)(((long long)(bid + 1) * NDIM) / NBLOCKS);

    unsigned long long a01 = 0ull, a23 = 0ull;   // packed plain sum
    float amAcc = 0.0f;                          // mixed-vec plain-sum remainder
    float bAcc  = 0.0f;                          // s_i-weighted upper-dot + diag

    #pragma unroll 1
    for (int row = rowBeg; row < rowEnd; ++row) {
        const ulonglong2* row64 =
            reinterpret_cast<const ulonglong2*>(M + (size_t)row * NDIM);

        // Batch-issue the whole row: 8 independent coalesced LDG.128 (MLP=8),
        // streaming policy (evict-first; M is touched exactly once).
        ulonglong2 v[8];
        #pragma unroll
        for (int k = 0; k < 8; ++k) v[k] = __ldcs(row64 + tid + k * 256);

        const int vs = row >> 2;          // vec index containing the diagonal
        unsigned long long d01 = 0ull, d23 = 0ull;
        float dm = 0.0f;

        #pragma unroll
        for (int k = 0; k < 8; ++k) {
            const int j4 = tid + k * 256;
            const ulonglong2 vv = v[k];
            if (j4 > vs) {
                // strictly above diagonal: sum + dot (warp-uniform in all but one warp)
                const ulonglong2 tt = s64[j4];       // LDS.128, conflict-free
                add2(a01, vv.x);  add2(a23, vv.y);
                fma2(d01, vv.x, tt.x);  fma2(d23, vv.y, tt.y);
            } else if (j4 < vs) {
                // strictly below diagonal: sum only
                add2(a01, vv.x);  add2(a23, vv.y);
            } else {
                // the one vec containing the diagonal: element-wise selects
                const float vx = lo2(vv.x), vy = hi2(vv.x);
                const float vz = lo2(vv.y), vw = hi2(vv.y);
                const ulonglong2 tt = s64[j4];
                const float tx = lo2(tt.x), ty = hi2(tt.x);
                const float tz = lo2(tt.y), tw = hi2(tt.y);
                const int j = j4 * 4;
                amAcc += (vx + vy) + (vz + vw);
                const float w0 = (j + 0 > row) ? tx : ((j + 0 == row) ? 1.0f : 0.0f);
                const float w1 = (j + 1 > row) ? ty : ((j + 1 == row) ? 1.0f : 0.0f);
                const float w2 = (j + 2 > row) ? tz : ((j + 2 == row) ? 1.0f : 0.0f);
                const float w3 = (j + 3 > row) ? tw : ((j + 3 == row) ? 1.0f : 0.0f);
                dm += fmaf(vx, w0, fmaf(vy, w1, fmaf(vz, w2, vw * w3)));
            }
        }

        // Fold this row's dot, weighted by s_row.
        const float di = ((lo2(d01) + hi2(d01)) + (lo2(d23) + hi2(d23))) + dm;
        bAcc = fmaf(s_sh[row], di, bAcc);
    }

    float aAcc = ((lo2(a01) + hi2(a01)) + (lo2(a23) + hi2(a23))) + amAcc;

    // Warp shuffle reduction (deterministic).
    #pragma unroll
    for (int off = 16; off > 0; off >>= 1) {
        aAcc += __shfl_xor_sync(0xFFFFFFFFu, aAcc, off);
        bAcc += __shfl_xor_sync(0xFFFFFFFFu, bAcc, off);
    }
    if (lane == 0) { sA[wid] = aAcc; sB[wid] = bAcc; }
    __syncthreads();

    if (tid == 0) {
        float a = 0.f, b = 0.f;
        #pragma unroll
        for (int w = 0; w < THREADS / 32; ++w) { a += sA[w]; b += sB[w]; }
        g_partA[bid] = a;
        g_partB[bid] = b;
        __threadfence();
        const int prev = atomicAdd(&g_count, 1);
        s_isLast = (prev == NBLOCKS - 1);
    }
    __syncthreads();

    // Last block: deterministic final reduction in double (reuses s_sh space).
    if (s_isLast) {
        double* rA = reinterpret_cast<double*>(s_sh);
        double* rB = rA + THREADS;
        double a = 0.0, b = 0.0;
        #pragma unroll 2
        for (int k = tid; k < NBLOCKS; k += THREADS) {
            a += (double)g_partA[k];
            b += (double)g_partB[k];
        }
        rA[tid] = a;
        rB[tid] = b;
        __syncthreads();
        #pragma unroll
        for (int st = THREADS / 2; st > 0; st >>= 1) {
            if (tid < st) { rA[tid] += rA[tid + st]; rB[tid] += rB[tid + st]; }
            __syncthreads();
        }
        if (tid == 0) {
            // out = sum(M)/4 - 0.5 * (sum_{i<j} M_ij s_i s_j + sum_i M_ii s_i)
            out[0] = (float)(rA[0] * 0.25 - 0.5 * rB[0]);
            g_count = 0;   // reset for next graph replay
        }
    }
}

extern "C" void kernel_launch(void* const* d_in, const int* in_sizes, int n_in,
                              void* d_out, int out_size) {
    const float* M = (const float*)d_in[0];   // info_mtx [8192, 8192] fp32
    const float* s = (const float*)d_in[1];   // state [8192] fp32
    float* out = (float*)d_out;

    ising_fused<<<NBLOCKS, THREADS>>>(M, s, out);
}